// round 2
// baseline (speedup 1.0000x reference)
#include <cuda_runtime.h>

#define NN 100000
#define NE 1600000
#define EMB 128
#define CDIM 32

// ---------------- device scratch (static, no allocations) ----------------
__device__ __align__(16) float g_p[NN * EMB];  // p = h @ W1   (51.2 MB)
__device__ __align__(16) float g_q[NN * EMB];  // q = (1+eps)p + b1 + scatter(p)
__device__ float g_u[EMB];           // cW @ W1[128:160]
__device__ float g_v[EMB];           // cb @ W1[128:160]
__device__ float g_sum[EMB];
__device__ float g_sumsq[EMB];
__device__ float g_scale[EMB];
__device__ float g_shift[EMB];
__device__ int   g_ei_is64;          // 1 if edge_index is int64, 0 if int32

// ---------------- f32x2 packed math helpers (Blackwell FFMA2) ------------
__device__ __forceinline__ unsigned long long pk2(float a, float b) {
    unsigned long long r;
    asm("mov.b64 %0, {%1,%2};" : "=l"(r) : "f"(a), "f"(b));
    return r;
}
__device__ __forceinline__ void upk2(unsigned long long v, float& a, float& b) {
    asm("mov.b64 {%0,%1}, %2;" : "=f"(a), "=f"(b) : "l"(v));
}
__device__ __forceinline__ void fma2(unsigned long long& d, unsigned long long a, unsigned long long b) {
    asm("fma.rn.f32x2 %0, %1, %2, %0;" : "+l"(d) : "l"(a), "l"(b));
}

// ---------------- dtype detect: int64 edge buffer has zero high words ----
__global__ void detect_kernel(const int* __restrict__ ei32) {
    if (threadIdx.x == 0) {
        int all_zero = 1;
        for (int i = 1; i < 64; i += 2)
            if (ei32[i] != 0) all_zero = 0;
        g_ei_is64 = all_zero;
    }
}

// ---------------- tiny prep: u = cW@W1b, v = cb@W1b, zero stats ----------
__global__ void prep_uv_kernel(const float* __restrict__ cW,
                               const float* __restrict__ cb,
                               const float* __restrict__ W1) {
    int j = threadIdx.x;  // 128 threads
    float u = 0.f, v = 0.f;
#pragma unroll
    for (int t = 0; t < CDIM; t++) {
        float w = W1[(EMB + t) * EMB + j];
        u = fmaf(cW[t], w, u);
        v = fmaf(cb[t], w, v);
    }
    g_u[j] = u;
    g_v[j] = v;
    g_sum[j] = 0.f;
    g_sumsq[j] = 0.f;
}

// ---------------- GEMM A: p = x@W1a + c*u + v ; q = (1+eps)p + b1 --------
__global__ void __launch_bounds__(512) gemmA_kernel(
    const float* __restrict__ x, const float* __restrict__ c,
    const float* __restrict__ eps, const float* __restrict__ W1,
    const float* __restrict__ b1) {
    extern __shared__ float sm[];
    float* Ws = sm;                  // [128][128]
    float* Xt = sm + EMB * EMB;      // [128][64] transposed A tile

    int tid = threadIdx.x;
    int row0 = blockIdx.x * 64;

    float4* Ws4 = (float4*)Ws;
    const float4* W14 = (const float4*)W1;
    for (int i = tid; i < EMB * EMB / 4; i += 512) Ws4[i] = W14[i];

    const float4* X4 = (const float4*)x;
    for (int i = tid; i < 32 * 64; i += 512) {
        int ch = i >> 6;     // k-chunk (4 floats)
        int r  = i & 63;     // local row
        int row = row0 + r;
        float4 val = make_float4(0.f, 0.f, 0.f, 0.f);
        if (row < NN) val = X4[row * 32 + ch];
        int k = ch * 4;
        Xt[(k + 0) * 64 + r] = val.x;
        Xt[(k + 1) * 64 + r] = val.y;
        Xt[(k + 2) * 64 + r] = val.z;
        Xt[(k + 3) * 64 + r] = val.w;
    }
    __syncthreads();

    int cg = tid & 31;   // 4 cols each
    int rg = tid >> 5;   // 0..15, 4 rows each
    unsigned long long a0[4] = {0ull, 0ull, 0ull, 0ull};
    unsigned long long a1[4] = {0ull, 0ull, 0ull, 0ull};

#pragma unroll 4
    for (int k = 0; k < EMB; k++) {
        float4 w = Ws4[k * 32 + cg];
        unsigned long long z01 = *(const unsigned long long*)(Xt + k * 64 + rg * 4);
        unsigned long long z23 = *(const unsigned long long*)(Xt + k * 64 + rg * 4 + 2);
        unsigned long long w0 = pk2(w.x, w.x), w1 = pk2(w.y, w.y);
        unsigned long long w2 = pk2(w.z, w.z), w3 = pk2(w.w, w.w);
        fma2(a0[0], z01, w0); fma2(a0[1], z01, w1); fma2(a0[2], z01, w2); fma2(a0[3], z01, w3);
        fma2(a1[0], z23, w0); fma2(a1[1], z23, w1); fma2(a1[2], z23, w2); fma2(a1[3], z23, w3);
    }

    float o[4][4];
#pragma unroll
    for (int j = 0; j < 4; j++) {
        upk2(a0[j], o[0][j], o[1][j]);
        upk2(a1[j], o[2][j], o[3][j]);
    }

    float4 u4  = ((const float4*)g_u)[cg];
    float4 v4  = ((const float4*)g_v)[cg];
    float4 b14 = ((const float4*)b1)[cg];
    float ep = 1.0f + eps[0];

#pragma unroll
    for (int rr = 0; rr < 4; rr++) {
        int row = row0 + rg * 4 + rr;
        if (row < NN) {
            float cv = __ldg(c + row);
            float4 po, qo;
            po.x = fmaf(cv, u4.x, o[rr][0] + v4.x);
            po.y = fmaf(cv, u4.y, o[rr][1] + v4.y);
            po.z = fmaf(cv, u4.z, o[rr][2] + v4.z);
            po.w = fmaf(cv, u4.w, o[rr][3] + v4.w);
            qo.x = fmaf(ep, po.x, b14.x);
            qo.y = fmaf(ep, po.y, b14.y);
            qo.z = fmaf(ep, po.z, b14.z);
            qo.w = fmaf(ep, po.w, b14.w);
            ((float4*)g_p)[row * 32 + cg] = po;
            ((float4*)g_q)[row * 32 + cg] = qo;
        }
    }
}

// ---------------- scatter: q[dst] += p[src], one warp per edge -----------
__global__ void __launch_bounds__(256) scatter_kernel(const void* __restrict__ ei_raw) {
    int warp = blockIdx.x * 8 + (threadIdx.x >> 5);
    int lane = threadIdx.x & 31;
    int ebase = warp * 4;
    int is64 = g_ei_is64;   // uniform
    const long long* ei64 = (const long long*)ei_raw;
    const int*       ei32 = (const int*)ei_raw;
#pragma unroll
    for (int i = 0; i < 4; i++) {
        int e = ebase + i;
        if (e < NE) {
            int src, dst;
            if (is64) {
                src = (int)__ldg(ei64 + e);
                dst = (int)__ldg(ei64 + NE + e);
            } else {
                src = __ldg(ei32 + e);
                dst = __ldg(ei32 + NE + e);
            }
            float4 v = __ldg(((const float4*)g_p) + src * 32 + lane);
            float4* tgt = ((float4*)g_q) + dst * 32 + lane;
            asm volatile("red.global.add.v4.f32 [%0], {%1,%2,%3,%4};"
                         :: "l"(tgt), "f"(v.x), "f"(v.y), "f"(v.z), "f"(v.w)
                         : "memory");
        }
    }
}

// ---------------- BN stats over q: per-column sum / sumsq ----------------
__global__ void __launch_bounds__(256) stats_kernel() {
    __shared__ float ss[256], sq[256];
    long long gt = (long long)blockIdx.x * 256 + threadIdx.x;
    long long stride = (long long)gridDim.x * 256;
    float s = 0.f, q = 0.f;
    for (long long i = gt; i < (long long)NN * EMB; i += stride) {
        float v = g_q[i];
        s += v;
        q = fmaf(v, v, q);
    }
    ss[threadIdx.x] = s;
    sq[threadIdx.x] = q;
    __syncthreads();
    if (threadIdx.x < 128) {
        atomicAdd(&g_sum[threadIdx.x],   ss[threadIdx.x] + ss[threadIdx.x + 128]);
        atomicAdd(&g_sumsq[threadIdx.x], sq[threadIdx.x] + sq[threadIdx.x + 128]);
    }
}

// ---------------- finalize BN scale/shift ---------------------------------
__global__ void finalize_kernel(const float* __restrict__ gamma,
                                const float* __restrict__ beta) {
    int t = threadIdx.x;  // 128
    const float invN = 1.0f / (float)NN;
    float mu  = g_sum[t] * invN;
    float var = g_sumsq[t] * invN - mu * mu;
    float sc  = gamma[t] * rsqrtf(var + 1e-5f);
    g_scale[t] = sc;
    g_shift[t] = beta[t] - mu * sc;
}

// ---------------- GEMM 2: out = relu(bn(q)) @ W2 + b2 --------------------
__global__ void __launch_bounds__(512) gemm2_kernel(
    const float* __restrict__ W2, const float* __restrict__ b2,
    float* __restrict__ out) {
    extern __shared__ float sm[];
    float* Ws  = sm;                       // [128][128]
    float* Yt  = sm + EMB * EMB;           // [128][64]
    float* scs = Yt + EMB * 64;            // [128]
    float* shs = scs + 128;                // [128]

    int tid = threadIdx.x;
    int row0 = blockIdx.x * 64;

    if (tid < 128)      scs[tid] = g_scale[tid];
    else if (tid < 256) shs[tid - 128] = g_shift[tid - 128];

    float4* Ws4 = (float4*)Ws;
    const float4* W24 = (const float4*)W2;
    for (int i = tid; i < EMB * EMB / 4; i += 512) Ws4[i] = W24[i];
    __syncthreads();

    const float4* Q4 = (const float4*)g_q;
    for (int i = tid; i < 32 * 64; i += 512) {
        int ch = i >> 6, r = i & 63;
        int row = row0 + r;
        float4 v = make_float4(0.f, 0.f, 0.f, 0.f);
        if (row < NN) v = Q4[row * 32 + ch];
        int k = ch * 4;
        Yt[(k + 0) * 64 + r] = fmaxf(fmaf(v.x, scs[k + 0], shs[k + 0]), 0.f);
        Yt[(k + 1) * 64 + r] = fmaxf(fmaf(v.y, scs[k + 1], shs[k + 1]), 0.f);
        Yt[(k + 2) * 64 + r] = fmaxf(fmaf(v.z, scs[k + 2], shs[k + 2]), 0.f);
        Yt[(k + 3) * 64 + r] = fmaxf(fmaf(v.w, scs[k + 3], shs[k + 3]), 0.f);
    }
    __syncthreads();

    int cg = tid & 31;
    int rg = tid >> 5;
    unsigned long long a0[4] = {0ull, 0ull, 0ull, 0ull};
    unsigned long long a1[4] = {0ull, 0ull, 0ull, 0ull};

#pragma unroll 4
    for (int k = 0; k < EMB; k++) {
        float4 w = Ws4[k * 32 + cg];
        unsigned long long z01 = *(const unsigned long long*)(Yt + k * 64 + rg * 4);
        unsigned long long z23 = *(const unsigned long long*)(Yt + k * 64 + rg * 4 + 2);
        unsigned long long w0 = pk2(w.x, w.x), w1 = pk2(w.y, w.y);
        unsigned long long w2 = pk2(w.z, w.z), w3 = pk2(w.w, w.w);
        fma2(a0[0], z01, w0); fma2(a0[1], z01, w1); fma2(a0[2], z01, w2); fma2(a0[3], z01, w3);
        fma2(a1[0], z23, w0); fma2(a1[1], z23, w1); fma2(a1[2], z23, w2); fma2(a1[3], z23, w3);
    }

    float o[4][4];
#pragma unroll
    for (int j = 0; j < 4; j++) {
        upk2(a0[j], o[0][j], o[1][j]);
        upk2(a1[j], o[2][j], o[3][j]);
    }

    float4 b24 = ((const float4*)b2)[cg];
#pragma unroll
    for (int rr = 0; rr < 4; rr++) {
        int row = row0 + rg * 4 + rr;
        if (row < NN) {
            float4 ov;
            ov.x = o[rr][0] + b24.x;
            ov.y = o[rr][1] + b24.y;
            ov.z = o[rr][2] + b24.z;
            ov.w = o[rr][3] + b24.w;
            ((float4*)out)[row * 32 + cg] = ov;
        }
    }
}

// ---------------- launch ---------------------------------------------------
extern "C" void kernel_launch(void* const* d_in, const int* in_sizes, int n_in,
                              void* d_out, int out_size) {
    const float* x     = (const float*)d_in[0];
    const float* c     = (const float*)d_in[1];
    const void*  ei    = d_in[2];
    const float* cW    = (const float*)d_in[3];
    const float* cb    = (const float*)d_in[4];
    const float* eps   = (const float*)d_in[5];
    const float* W1    = (const float*)d_in[6];
    const float* b1    = (const float*)d_in[7];
    const float* gamma = (const float*)d_in[8];
    const float* beta  = (const float*)d_in[9];
    const float* W2    = (const float*)d_in[10];
    const float* b2    = (const float*)d_in[11];
    float* out = (float*)d_out;

    const int SMEM_A = (EMB * EMB + EMB * 64) * 4;          // 98304
    const int SMEM_2 = (EMB * EMB + EMB * 64 + 256) * 4;    // 99328
    cudaFuncSetAttribute(gemmA_kernel, cudaFuncAttributeMaxDynamicSharedMemorySize, SMEM_A);
    cudaFuncSetAttribute(gemm2_kernel, cudaFuncAttributeMaxDynamicSharedMemorySize, SMEM_2);

    int gemm_blocks = (NN + 63) / 64;  // 1563

    detect_kernel<<<1, 32>>>((const int*)ei);
    prep_uv_kernel<<<1, 128>>>(cW, cb, W1);
    gemmA_kernel<<<gemm_blocks, 512, SMEM_A>>>(x, c, eps, W1, b1);
    scatter_kernel<<<NE / 32, 256>>>(ei);   // 8 warps/block * 4 edges/warp
    stats_kernel<<<296, 256>>>();
    finalize_kernel<<<1, 128>>>(gamma, beta);
    gemm2_kernel<<<gemm_blocks, 512, SMEM_2>>>(W2, b2, out);
}

// round 3
// speedup vs baseline: 1.0855x; 1.0855x over previous
#include <cuda_runtime.h>

#define NN 100000
#define NE 1600000
#define EMB 128
#define CDIM 32
#define NNP 100096          // 391 * 256
#define NBLK_SCAN 391
#define MT 256              // gemm row tile

typedef unsigned long long ull;

// ---------------- device scratch (static, no allocations) ----------------
__device__ __align__(16) float g_p[NN * EMB];   // p = h @ W1
__device__ __align__(16) float g_q[NN * EMB];   // q = (1+eps)p + b1 (+agg)
__device__ int   g_srcs[NE];       // CSR: src per incoming edge, grouped by dst
__device__ int   g_cnt[NNP];
__device__ int   g_offA[NNP];
__device__ int   g_off[NN + 1];
__device__ int   g_cur[NN];
__device__ int   g_bsum[NBLK_SCAN];
__device__ int   g_bsumx[NBLK_SCAN];
__device__ float g_u[EMB], g_v[EMB];
__device__ float g_sum[EMB], g_sumsq[EMB];
__device__ float g_scale[EMB], g_shift[EMB];
__device__ int   g_ei_is64;

// ---------------- f32x2 packed helpers -----------------------------------
__device__ __forceinline__ ull pk2(float a, float b) {
    ull r;
    asm("mov.b64 %0, {%1,%2};" : "=l"(r) : "f"(a), "f"(b));
    return r;
}
__device__ __forceinline__ void upk2(ull v, float& a, float& b) {
    asm("mov.b64 {%0,%1}, %2;" : "=f"(a), "=f"(b) : "l"(v));
}
__device__ __forceinline__ void fma2(ull& d, ull a, ull b) {
    asm("fma.rn.f32x2 %0, %1, %2, %0;" : "+l"(d) : "l"(a), "l"(b));
}

// ---------------- dtype detect -------------------------------------------
__global__ void detect_kernel(const int* __restrict__ ei32) {
    if (threadIdx.x == 0) {
        int all_zero = 1;
        for (int i = 1; i < 64; i += 2)
            if (ei32[i] != 0) all_zero = 0;
        g_ei_is64 = all_zero;
    }
}

// ---------------- prep: u,v and zero stats --------------------------------
__global__ void prep_uv_kernel(const float* __restrict__ cW,
                               const float* __restrict__ cb,
                               const float* __restrict__ W1) {
    int j = threadIdx.x;  // 128
    float u = 0.f, v = 0.f;
#pragma unroll
    for (int t = 0; t < CDIM; t++) {
        float w = W1[(EMB + t) * EMB + j];
        u = fmaf(cW[t], w, u);
        v = fmaf(cb[t], w, v);
    }
    g_u[j] = u; g_v[j] = v;
    g_sum[j] = 0.f; g_sumsq[j] = 0.f;
}

__global__ void zero_cnt_kernel() {
    int i = blockIdx.x * 256 + threadIdx.x;
    if (i < NNP) g_cnt[i] = 0;
}

// ---------------- CSR build ------------------------------------------------
__global__ void hist_kernel(const void* __restrict__ ei_raw) {
    int is64 = g_ei_is64;
    const long long* e64 = (const long long*)ei_raw;
    const int*       e32 = (const int*)ei_raw;
    for (int e = blockIdx.x * blockDim.x + threadIdx.x; e < NE;
         e += gridDim.x * blockDim.x) {
        int dst = is64 ? (int)__ldg(e64 + NE + e) : __ldg(e32 + NE + e);
        atomicAdd(&g_cnt[dst], 1);
    }
}

template <int NW>
__device__ __forceinline__ int block_scan_incl(int v, int* ws) {
    int lane = threadIdx.x & 31, w = threadIdx.x >> 5;
#pragma unroll
    for (int d = 1; d < 32; d <<= 1) {
        int n = __shfl_up_sync(0xffffffffu, v, d);
        if (lane >= d) v += n;
    }
    if (lane == 31) ws[w] = v;
    __syncthreads();
    if (w == 0) {
        int s = (lane < NW) ? ws[lane] : 0;
#pragma unroll
        for (int d = 1; d < 32; d <<= 1) {
            int n = __shfl_up_sync(0xffffffffu, s, d);
            if (lane >= d) s += n;
        }
        if (lane < NW) ws[lane] = s;
    }
    __syncthreads();
    if (w > 0) v += ws[w - 1];
    return v;
}

__global__ void __launch_bounds__(256) scan1_kernel() {
    __shared__ int ws[8];
    int idx = blockIdx.x * 256 + threadIdx.x;
    int v = g_cnt[idx];
    int incl = block_scan_incl<8>(v, ws);
    g_offA[idx] = incl - v;
    if (threadIdx.x == 255) g_bsum[blockIdx.x] = incl;
}

__global__ void __launch_bounds__(512) scan2_kernel() {
    __shared__ int ws[16];
    int t = threadIdx.x;
    int v = (t < NBLK_SCAN) ? g_bsum[t] : 0;
    int incl = block_scan_incl<16>(v, ws);
    if (t < NBLK_SCAN) g_bsumx[t] = incl - v;
}

__global__ void __launch_bounds__(256) scan3_kernel() {
    int idx = blockIdx.x * 256 + threadIdx.x;
    if (idx < NN) {
        int o = g_offA[idx] + g_bsumx[idx >> 8];
        g_off[idx] = o;
        g_cur[idx] = o;
    }
    if (idx == 0) g_off[NN] = NE;
}

__global__ void fill_kernel(const void* __restrict__ ei_raw) {
    int is64 = g_ei_is64;
    const long long* e64 = (const long long*)ei_raw;
    const int*       e32 = (const int*)ei_raw;
    for (int e = blockIdx.x * blockDim.x + threadIdx.x; e < NE;
         e += gridDim.x * blockDim.x) {
        int src, dst;
        if (is64) {
            src = (int)__ldg(e64 + e);
            dst = (int)__ldg(e64 + NE + e);
        } else {
            src = __ldg(e32 + e);
            dst = __ldg(e32 + NE + e);
        }
        int pos = atomicAdd(&g_cur[dst], 1);
        g_srcs[pos] = src;
    }
}

// ---------------- GEMM A: p = x@W1a + c*u + v ; q = (1+eps)p + b1 --------
// 256-row x 128-col tile, 512 threads, 8x8 per thread via f32x2.
__global__ void __launch_bounds__(512) gemmA_kernel(
    const float* __restrict__ x, const float* __restrict__ c,
    const float* __restrict__ eps, const float* __restrict__ W1,
    const float* __restrict__ b1) {
    extern __shared__ float sm[];
    float* Ws = sm;               // [128][128]
    float* Xs = sm + EMB * EMB;   // [256][128] row-major

    int tid = threadIdx.x;
    int row0 = blockIdx.x * MT;

    float4* Ws4 = (float4*)Ws;
    const float4* W14 = (const float4*)W1;
    for (int i = tid; i < EMB * EMB / 4; i += 512) Ws4[i] = W14[i];

    float4* Xs4 = (float4*)Xs;
    const float4* X4 = (const float4*)x;
    for (int i = tid; i < MT * 32; i += 512) {
        int r = i >> 5, ch = i & 31;
        int row = row0 + r;
        Xs4[i] = (row < NN) ? X4[row * 32 + ch] : make_float4(0.f, 0.f, 0.f, 0.f);
    }
    __syncthreads();

    int cg = tid & 15;    // cols cg*8 .. cg*8+7
    int rg = tid >> 4;    // rows rg*8 .. rg*8+7 (0..31)
    ull acc[8][4];
#pragma unroll
    for (int j = 0; j < 8; j++)
#pragma unroll
        for (int q = 0; q < 4; q++) acc[j][q] = 0ull;

    const float* zb = Xs + rg * 8 * EMB;
#pragma unroll 4
    for (int k = 0; k < EMB; k++) {
        const ull* wp = (const ull*)(Ws + k * EMB + cg * 8);
        ull w01 = wp[0], w23 = wp[1], w45 = wp[2], w67 = wp[3];
#pragma unroll
        for (int j = 0; j < 8; j++) {
            float z = zb[j * EMB + k];
            ull zz = pk2(z, z);
            fma2(acc[j][0], zz, w01);
            fma2(acc[j][1], zz, w23);
            fma2(acc[j][2], zz, w45);
            fma2(acc[j][3], zz, w67);
        }
    }

    float4 uA = ((const float4*)g_u)[cg * 2], uB = ((const float4*)g_u)[cg * 2 + 1];
    float4 vA = ((const float4*)g_v)[cg * 2], vB = ((const float4*)g_v)[cg * 2 + 1];
    float4 bA = ((const float4*)b1)[cg * 2],  bB = ((const float4*)b1)[cg * 2 + 1];
    float ep = 1.0f + eps[0];

#pragma unroll
    for (int j = 0; j < 8; j++) {
        int row = row0 + rg * 8 + j;
        if (row < NN) {
            float o[8];
            upk2(acc[j][0], o[0], o[1]);
            upk2(acc[j][1], o[2], o[3]);
            upk2(acc[j][2], o[4], o[5]);
            upk2(acc[j][3], o[6], o[7]);
            float cv = __ldg(c + row);
            float4 pA, pB, qA, qB;
            pA.x = fmaf(cv, uA.x, o[0] + vA.x);
            pA.y = fmaf(cv, uA.y, o[1] + vA.y);
            pA.z = fmaf(cv, uA.z, o[2] + vA.z);
            pA.w = fmaf(cv, uA.w, o[3] + vA.w);
            pB.x = fmaf(cv, uB.x, o[4] + vB.x);
            pB.y = fmaf(cv, uB.y, o[5] + vB.y);
            pB.z = fmaf(cv, uB.z, o[6] + vB.z);
            pB.w = fmaf(cv, uB.w, o[7] + vB.w);
            qA.x = fmaf(ep, pA.x, bA.x); qA.y = fmaf(ep, pA.y, bA.y);
            qA.z = fmaf(ep, pA.z, bA.z); qA.w = fmaf(ep, pA.w, bA.w);
            qB.x = fmaf(ep, pB.x, bB.x); qB.y = fmaf(ep, pB.y, bB.y);
            qB.z = fmaf(ep, pB.z, bB.z); qB.w = fmaf(ep, pB.w, bB.w);
            ((float4*)g_p)[row * 32 + cg * 2]     = pA;
            ((float4*)g_p)[row * 32 + cg * 2 + 1] = pB;
            ((float4*)g_q)[row * 32 + cg * 2]     = qA;
            ((float4*)g_q)[row * 32 + cg * 2 + 1] = qB;
        }
    }
}

// ---------------- gather: q[n] += sum p[srcs], fused BN stats -------------
__global__ void __launch_bounds__(256) gather_kernel() {
    __shared__ float s_sum[EMB], s_sq[EMB];
    int tid = threadIdx.x;
    if (tid < EMB) { s_sum[tid] = 0.f; s_sq[tid] = 0.f; }
    __syncthreads();

    int lane = tid & 31;
    int gw = blockIdx.x * 8 + (tid >> 5);
    int nw = gridDim.x * 8;
    const float4* P4 = (const float4*)g_p;
    float4* Q4 = (float4*)g_q;

    float4 csum = make_float4(0.f, 0.f, 0.f, 0.f);
    float4 csq  = make_float4(0.f, 0.f, 0.f, 0.f);

    for (int n = gw; n < NN; n += nw) {
        int s0 = g_off[n], s1 = g_off[n + 1];
        float4 acc = Q4[n * 32 + lane];
        int e = s0;
        for (; e + 1 < s1; e += 2) {
            int src0 = g_srcs[e], src1 = g_srcs[e + 1];
            float4 v0 = P4[src0 * 32 + lane];
            float4 v1 = P4[src1 * 32 + lane];
            acc.x += v0.x + v1.x; acc.y += v0.y + v1.y;
            acc.z += v0.z + v1.z; acc.w += v0.w + v1.w;
        }
        if (e < s1) {
            float4 v = P4[g_srcs[e] * 32 + lane];
            acc.x += v.x; acc.y += v.y; acc.z += v.z; acc.w += v.w;
        }
        Q4[n * 32 + lane] = acc;
        csum.x += acc.x; csum.y += acc.y; csum.z += acc.z; csum.w += acc.w;
        csq.x  = fmaf(acc.x, acc.x, csq.x);
        csq.y  = fmaf(acc.y, acc.y, csq.y);
        csq.z  = fmaf(acc.z, acc.z, csq.z);
        csq.w  = fmaf(acc.w, acc.w, csq.w);
    }

    atomicAdd(&s_sum[lane * 4 + 0], csum.x);
    atomicAdd(&s_sum[lane * 4 + 1], csum.y);
    atomicAdd(&s_sum[lane * 4 + 2], csum.z);
    atomicAdd(&s_sum[lane * 4 + 3], csum.w);
    atomicAdd(&s_sq[lane * 4 + 0], csq.x);
    atomicAdd(&s_sq[lane * 4 + 1], csq.y);
    atomicAdd(&s_sq[lane * 4 + 2], csq.z);
    atomicAdd(&s_sq[lane * 4 + 3], csq.w);
    __syncthreads();
    if (tid < EMB) {
        atomicAdd(&g_sum[tid],   s_sum[tid]);
        atomicAdd(&g_sumsq[tid], s_sq[tid]);
    }
}

// ---------------- finalize BN scale/shift ---------------------------------
__global__ void finalize_kernel(const float* __restrict__ gamma,
                                const float* __restrict__ beta) {
    int t = threadIdx.x;
    const float invN = 1.0f / (float)NN;
    float mu  = g_sum[t] * invN;
    float var = g_sumsq[t] * invN - mu * mu;
    float sc  = gamma[t] * rsqrtf(var + 1e-5f);
    g_scale[t] = sc;
    g_shift[t] = beta[t] - mu * sc;
}

// ---------------- GEMM 2: out = relu(bn(q)) @ W2 + b2 --------------------
__global__ void __launch_bounds__(512) gemm2_kernel(
    const float* __restrict__ W2, const float* __restrict__ b2,
    float* __restrict__ out) {
    extern __shared__ float sm[];
    float* Ws  = sm;                        // [128][128]
    float* Ys  = sm + EMB * EMB;            // [256][128]
    float* scs = Ys + MT * EMB;             // [128]
    float* shs = scs + EMB;                 // [128]

    int tid = threadIdx.x;
    int row0 = blockIdx.x * MT;

    if (tid < EMB)            scs[tid] = g_scale[tid];
    else if (tid < 2 * EMB)   shs[tid - EMB] = g_shift[tid - EMB];

    float4* Ws4 = (float4*)Ws;
    const float4* W24 = (const float4*)W2;
    for (int i = tid; i < EMB * EMB / 4; i += 512) Ws4[i] = W24[i];
    __syncthreads();

    float4* Ys4 = (float4*)Ys;
    const float4* Q4 = (const float4*)g_q;
    for (int i = tid; i < MT * 32; i += 512) {
        int r = i >> 5, ch = i & 31;
        int row = row0 + r;
        float4 v = (row < NN) ? Q4[row * 32 + ch] : make_float4(0.f, 0.f, 0.f, 0.f);
        int k0 = ch * 4;
        v.x = fmaxf(fmaf(v.x, scs[k0 + 0], shs[k0 + 0]), 0.f);
        v.y = fmaxf(fmaf(v.y, scs[k0 + 1], shs[k0 + 1]), 0.f);
        v.z = fmaxf(fmaf(v.z, scs[k0 + 2], shs[k0 + 2]), 0.f);
        v.w = fmaxf(fmaf(v.w, scs[k0 + 3], shs[k0 + 3]), 0.f);
        Ys4[i] = v;
    }
    __syncthreads();

    int cg = tid & 15;
    int rg = tid >> 4;
    ull acc[8][4];
#pragma unroll
    for (int j = 0; j < 8; j++)
#pragma unroll
        for (int q = 0; q < 4; q++) acc[j][q] = 0ull;

    const float* zb = Ys + rg * 8 * EMB;
#pragma unroll 4
    for (int k = 0; k < EMB; k++) {
        const ull* wp = (const ull*)(Ws + k * EMB + cg * 8);
        ull w01 = wp[0], w23 = wp[1], w45 = wp[2], w67 = wp[3];
#pragma unroll
        for (int j = 0; j < 8; j++) {
            float z = zb[j * EMB + k];
            ull zz = pk2(z, z);
            fma2(acc[j][0], zz, w01);
            fma2(acc[j][1], zz, w23);
            fma2(acc[j][2], zz, w45);
            fma2(acc[j][3], zz, w67);
        }
    }

    float4 bA = ((const float4*)b2)[cg * 2], bB = ((const float4*)b2)[cg * 2 + 1];
#pragma unroll
    for (int j = 0; j < 8; j++) {
        int row = row0 + rg * 8 + j;
        if (row < NN) {
            float o[8];
            upk2(acc[j][0], o[0], o[1]);
            upk2(acc[j][1], o[2], o[3]);
            upk2(acc[j][2], o[4], o[5]);
            upk2(acc[j][3], o[6], o[7]);
            float4 oA, oB;
            oA.x = o[0] + bA.x; oA.y = o[1] + bA.y;
            oA.z = o[2] + bA.z; oA.w = o[3] + bA.w;
            oB.x = o[4] + bB.x; oB.y = o[5] + bB.y;
            oB.z = o[6] + bB.z; oB.w = o[7] + bB.w;
            ((float4*)out)[row * 32 + cg * 2]     = oA;
            ((float4*)out)[row * 32 + cg * 2 + 1] = oB;
        }
    }
}

// ---------------- launch ---------------------------------------------------
extern "C" void kernel_launch(void* const* d_in, const int* in_sizes, int n_in,
                              void* d_out, int out_size) {
    const float* x     = (const float*)d_in[0];
    const float* c     = (const float*)d_in[1];
    const void*  ei    = d_in[2];
    const float* cW    = (const float*)d_in[3];
    const float* cb    = (const float*)d_in[4];
    const float* eps   = (const float*)d_in[5];
    const float* W1    = (const float*)d_in[6];
    const float* b1    = (const float*)d_in[7];
    const float* gamma = (const float*)d_in[8];
    const float* beta  = (const float*)d_in[9];
    const float* W2    = (const float*)d_in[10];
    const float* b2    = (const float*)d_in[11];
    float* out = (float*)d_out;

    const int SMEM_A = (EMB * EMB + MT * EMB) * 4;            // 196608
    const int SMEM_2 = (EMB * EMB + MT * EMB + 2 * EMB) * 4;  // 197632
    cudaFuncSetAttribute(gemmA_kernel, cudaFuncAttributeMaxDynamicSharedMemorySize, SMEM_A);
    cudaFuncSetAttribute(gemm2_kernel, cudaFuncAttributeMaxDynamicSharedMemorySize, SMEM_2);

    int gemm_blocks = (NN + MT - 1) / MT;  // 391

    detect_kernel<<<1, 32>>>((const int*)ei);
    prep_uv_kernel<<<1, 128>>>(cW, cb, W1);
    zero_cnt_kernel<<<NNP / 256, 256>>>();
    hist_kernel<<<1024, 256>>>(ei);
    scan1_kernel<<<NBLK_SCAN, 256>>>();
    scan2_kernel<<<1, 512>>>();
    scan3_kernel<<<NBLK_SCAN, 256>>>();
    fill_kernel<<<1024, 256>>>(ei);
    gemmA_kernel<<<gemm_blocks, 512, SMEM_A>>>(x, c, eps, W1, b1);
    gather_kernel<<<1184, 256>>>();
    finalize_kernel<<<1, 128>>>(gamma, beta);
    gemm2_kernel<<<gemm_blocks, 512, SMEM_2>>>(W2, b2, out);
}

// round 4
// speedup vs baseline: 1.2581x; 1.1590x over previous
#include <cuda_runtime.h>

#define NN 100000
#define NE 1600000
#define EMB 128
#define CDIM 32
#define NNP 100096          // 391 * 256
#define NBLK_SCAN 391
#define MT 256              // gemm row tile

typedef unsigned long long ull;

// ---------------- device scratch (static, no allocations) ----------------
__device__ __align__(16) float g_p[NN * EMB];   // p = h @ W1
__device__ __align__(16) float g_q[NN * EMB];   // q = (1+eps)p + b1 + agg
__device__ int   g_srcs[NE];       // CSR: src per incoming edge, grouped by dst
__device__ int   g_cnt[NNP];
__device__ int   g_offA[NNP];
__device__ int   g_off[NN + 1];
__device__ int   g_cur[NN];
__device__ int   g_bsum[NBLK_SCAN];
__device__ int   g_bsumx[NBLK_SCAN];
__device__ float g_u[EMB], g_v[EMB];
__device__ float g_sum[EMB], g_sumsq[EMB];
__device__ float g_scale[EMB], g_shift[EMB];
__device__ int   g_ei_is64;

// ---------------- f32x2 packed helpers -----------------------------------
__device__ __forceinline__ ull pk2(float a, float b) {
    ull r;
    asm("mov.b64 %0, {%1,%2};" : "=l"(r) : "f"(a), "f"(b));
    return r;
}
__device__ __forceinline__ void upk2(ull v, float& a, float& b) {
    asm("mov.b64 {%0,%1}, %2;" : "=f"(a), "=f"(b) : "l"(v));
}
__device__ __forceinline__ void fma2(ull& d, ull a, ull b) {
    asm("fma.rn.f32x2 %0, %1, %2, %0;" : "+l"(d) : "l"(a), "l"(b));
}

// ---------------- init: zero counts + dtype detect + u,v prep ------------
__global__ void __launch_bounds__(256) init_kernel(
    const int* __restrict__ ei32, const float* __restrict__ cW,
    const float* __restrict__ cb, const float* __restrict__ W1) {
    int i = blockIdx.x * 256 + threadIdx.x;
    if (i < NNP) g_cnt[i] = 0;
    if (blockIdx.x == 0) {
        int t = threadIdx.x;
        if (t < EMB) {
            float u = 0.f, v = 0.f;
#pragma unroll
            for (int k = 0; k < CDIM; k++) {
                float w = W1[(EMB + k) * EMB + t];
                u = fmaf(cW[k], w, u);
                v = fmaf(cb[k], w, v);
            }
            g_u[t] = u; g_v[t] = v;
            g_sum[t] = 0.f; g_sumsq[t] = 0.f;
        }
        if (t == 0) {
            int all_zero = 1;
            for (int j = 1; j < 64; j += 2)
                if (ei32[j] != 0) all_zero = 0;
            g_ei_is64 = all_zero;
        }
    }
}

// ---------------- CSR build ------------------------------------------------
__global__ void hist_kernel(const void* __restrict__ ei_raw) {
    int is64 = g_ei_is64;
    const long long* e64 = (const long long*)ei_raw;
    const int*       e32 = (const int*)ei_raw;
    for (int e = blockIdx.x * blockDim.x + threadIdx.x; e < NE;
         e += gridDim.x * blockDim.x) {
        int dst = is64 ? (int)__ldg(e64 + NE + e) : __ldg(e32 + NE + e);
        atomicAdd(&g_cnt[dst], 1);
    }
}

template <int NW>
__device__ __forceinline__ int block_scan_incl(int v, int* ws) {
    int lane = threadIdx.x & 31, w = threadIdx.x >> 5;
#pragma unroll
    for (int d = 1; d < 32; d <<= 1) {
        int n = __shfl_up_sync(0xffffffffu, v, d);
        if (lane >= d) v += n;
    }
    if (lane == 31) ws[w] = v;
    __syncthreads();
    if (w == 0) {
        int s = (lane < NW) ? ws[lane] : 0;
#pragma unroll
        for (int d = 1; d < 32; d <<= 1) {
            int n = __shfl_up_sync(0xffffffffu, s, d);
            if (lane >= d) s += n;
        }
        if (lane < NW) ws[lane] = s;
    }
    __syncthreads();
    if (w > 0) v += ws[w - 1];
    return v;
}

__global__ void __launch_bounds__(256) scan1_kernel() {
    __shared__ int ws[8];
    int idx = blockIdx.x * 256 + threadIdx.x;
    int v = g_cnt[idx];
    int incl = block_scan_incl<8>(v, ws);
    g_offA[idx] = incl - v;
    if (threadIdx.x == 255) g_bsum[blockIdx.x] = incl;
}

__global__ void __launch_bounds__(512) scan2_kernel() {
    __shared__ int ws[16];
    int t = threadIdx.x;
    int v = (t < NBLK_SCAN) ? g_bsum[t] : 0;
    int incl = block_scan_incl<16>(v, ws);
    if (t < NBLK_SCAN) g_bsumx[t] = incl - v;
}

__global__ void __launch_bounds__(256) scan3_kernel() {
    int idx = blockIdx.x * 256 + threadIdx.x;
    if (idx < NN) {
        int o = g_offA[idx] + g_bsumx[idx >> 8];
        g_off[idx] = o;
        g_cur[idx] = o;
    }
    if (idx == 0) g_off[NN] = NE;
}

__global__ void fill_kernel(const void* __restrict__ ei_raw) {
    int is64 = g_ei_is64;
    const long long* e64 = (const long long*)ei_raw;
    const int*       e32 = (const int*)ei_raw;
    for (int e = blockIdx.x * blockDim.x + threadIdx.x; e < NE;
         e += gridDim.x * blockDim.x) {
        int src, dst;
        if (is64) {
            src = (int)__ldg(e64 + e);
            dst = (int)__ldg(e64 + NE + e);
        } else {
            src = __ldg(e32 + e);
            dst = __ldg(e32 + NE + e);
        }
        int pos = atomicAdd(&g_cur[dst], 1);
        g_srcs[pos] = src;
    }
}

// ---------------- GEMM A: p = x@W1a + c*u + v ------------------------------
// 256-row x 128-col tile, 512 threads, 8x8 per thread via f32x2.
__global__ void __launch_bounds__(512) gemmA_kernel(
    const float* __restrict__ x, const float* __restrict__ c,
    const float* __restrict__ W1) {
    extern __shared__ float sm[];
    float* Ws = sm;               // [128][128]
    float* Xs = sm + EMB * EMB;   // [256][128] row-major

    int tid = threadIdx.x;
    int row0 = blockIdx.x * MT;

    float4* Ws4 = (float4*)Ws;
    const float4* W14 = (const float4*)W1;
    for (int i = tid; i < EMB * EMB / 4; i += 512) Ws4[i] = W14[i];

    float4* Xs4 = (float4*)Xs;
    const float4* X4 = (const float4*)x;
    for (int i = tid; i < MT * 32; i += 512) {
        int r = i >> 5, ch = i & 31;
        int row = row0 + r;
        Xs4[i] = (row < NN) ? X4[row * 32 + ch] : make_float4(0.f, 0.f, 0.f, 0.f);
    }
    __syncthreads();

    int cg = tid & 15;    // cols cg*8 .. cg*8+7
    int rg = tid >> 4;    // rows rg*8 .. rg*8+7 (0..31)
    ull acc[8][4];
#pragma unroll
    for (int j = 0; j < 8; j++)
#pragma unroll
        for (int q = 0; q < 4; q++) acc[j][q] = 0ull;

    const float* zb = Xs + rg * 8 * EMB;
#pragma unroll 4
    for (int k = 0; k < EMB; k++) {
        const ull* wp = (const ull*)(Ws + k * EMB + cg * 8);
        ull w01 = wp[0], w23 = wp[1], w45 = wp[2], w67 = wp[3];
#pragma unroll
        for (int j = 0; j < 8; j++) {
            float z = zb[j * EMB + k];
            ull zz = pk2(z, z);
            fma2(acc[j][0], zz, w01);
            fma2(acc[j][1], zz, w23);
            fma2(acc[j][2], zz, w45);
            fma2(acc[j][3], zz, w67);
        }
    }

    float4 uA = ((const float4*)g_u)[cg * 2], uB = ((const float4*)g_u)[cg * 2 + 1];
    float4 vA = ((const float4*)g_v)[cg * 2], vB = ((const float4*)g_v)[cg * 2 + 1];

#pragma unroll
    for (int j = 0; j < 8; j++) {
        int row = row0 + rg * 8 + j;
        if (row < NN) {
            float o[8];
            upk2(acc[j][0], o[0], o[1]);
            upk2(acc[j][1], o[2], o[3]);
            upk2(acc[j][2], o[4], o[5]);
            upk2(acc[j][3], o[6], o[7]);
            float cv = __ldg(c + row);
            float4 pA, pB;
            pA.x = fmaf(cv, uA.x, o[0] + vA.x);
            pA.y = fmaf(cv, uA.y, o[1] + vA.y);
            pA.z = fmaf(cv, uA.z, o[2] + vA.z);
            pA.w = fmaf(cv, uA.w, o[3] + vA.w);
            pB.x = fmaf(cv, uB.x, o[4] + vB.x);
            pB.y = fmaf(cv, uB.y, o[5] + vB.y);
            pB.z = fmaf(cv, uB.z, o[6] + vB.z);
            pB.w = fmaf(cv, uB.w, o[7] + vB.w);
            ((float4*)g_p)[row * 32 + cg * 2]     = pA;
            ((float4*)g_p)[row * 32 + cg * 2 + 1] = pB;
        }
    }
}

// ---------------- gather: q[n] = (1+eps)p[n]+b1 + sum p[srcs], + BN stats --
__global__ void __launch_bounds__(256) gather_kernel(
    const float* __restrict__ eps, const float* __restrict__ b1) {
    __shared__ float s_sum[EMB], s_sq[EMB];
    int tid = threadIdx.x;
    if (tid < EMB) { s_sum[tid] = 0.f; s_sq[tid] = 0.f; }
    __syncthreads();

    int lane = tid & 31;
    int gw = blockIdx.x * 8 + (tid >> 5);
    int nw = gridDim.x * 8;
    const float4* P4 = (const float4*)g_p;
    float4* Q4 = (float4*)g_q;

    float ep = 1.0f + __ldg(eps);
    float4 b1v = __ldg(((const float4*)b1) + lane);

    float4 csum = make_float4(0.f, 0.f, 0.f, 0.f);
    float4 csq  = make_float4(0.f, 0.f, 0.f, 0.f);

    for (int n = gw; n < NN; n += nw) {
        int s0 = g_off[n], s1 = g_off[n + 1];
        float4 pn = __ldg(P4 + n * 32 + lane);
        float4 a0, a1;
        a0.x = fmaf(ep, pn.x, b1v.x);
        a0.y = fmaf(ep, pn.y, b1v.y);
        a0.z = fmaf(ep, pn.z, b1v.z);
        a0.w = fmaf(ep, pn.w, b1v.w);
        a1 = make_float4(0.f, 0.f, 0.f, 0.f);
        int e = s0;
        for (; e + 3 < s1; e += 4) {
            int i0 = g_srcs[e],     i1 = g_srcs[e + 1];
            int i2 = g_srcs[e + 2], i3 = g_srcs[e + 3];
            float4 v0 = __ldg(P4 + i0 * 32 + lane);
            float4 v1 = __ldg(P4 + i1 * 32 + lane);
            float4 v2 = __ldg(P4 + i2 * 32 + lane);
            float4 v3 = __ldg(P4 + i3 * 32 + lane);
            a0.x += v0.x + v1.x; a0.y += v0.y + v1.y;
            a0.z += v0.z + v1.z; a0.w += v0.w + v1.w;
            a1.x += v2.x + v3.x; a1.y += v2.y + v3.y;
            a1.z += v2.z + v3.z; a1.w += v2.w + v3.w;
        }
        for (; e < s1; e++) {
            float4 v = __ldg(P4 + g_srcs[e] * 32 + lane);
            a1.x += v.x; a1.y += v.y; a1.z += v.z; a1.w += v.w;
        }
        float4 acc;
        acc.x = a0.x + a1.x; acc.y = a0.y + a1.y;
        acc.z = a0.z + a1.z; acc.w = a0.w + a1.w;
        Q4[n * 32 + lane] = acc;
        csum.x += acc.x; csum.y += acc.y; csum.z += acc.z; csum.w += acc.w;
        csq.x = fmaf(acc.x, acc.x, csq.x);
        csq.y = fmaf(acc.y, acc.y, csq.y);
        csq.z = fmaf(acc.z, acc.z, csq.z);
        csq.w = fmaf(acc.w, acc.w, csq.w);
    }

    atomicAdd(&s_sum[lane * 4 + 0], csum.x);
    atomicAdd(&s_sum[lane * 4 + 1], csum.y);
    atomicAdd(&s_sum[lane * 4 + 2], csum.z);
    atomicAdd(&s_sum[lane * 4 + 3], csum.w);
    atomicAdd(&s_sq[lane * 4 + 0], csq.x);
    atomicAdd(&s_sq[lane * 4 + 1], csq.y);
    atomicAdd(&s_sq[lane * 4 + 2], csq.z);
    atomicAdd(&s_sq[lane * 4 + 3], csq.w);
    __syncthreads();
    if (tid < EMB) {
        atomicAdd(&g_sum[tid],   s_sum[tid]);
        atomicAdd(&g_sumsq[tid], s_sq[tid]);
    }
}

// ---------------- finalize BN scale/shift ---------------------------------
__global__ void finalize_kernel(const float* __restrict__ gamma,
                                const float* __restrict__ beta) {
    int t = threadIdx.x;
    const float invN = 1.0f / (float)NN;
    float mu  = g_sum[t] * invN;
    float var = g_sumsq[t] * invN - mu * mu;
    float sc  = gamma[t] * rsqrtf(var + 1e-5f);
    g_scale[t] = sc;
    g_shift[t] = beta[t] - mu * sc;
}

// ---------------- GEMM 2: out = relu(bn(q)) @ W2 + b2 --------------------
__global__ void __launch_bounds__(512) gemm2_kernel(
    const float* __restrict__ W2, const float* __restrict__ b2,
    float* __restrict__ out) {
    extern __shared__ float sm[];
    float* Ws  = sm;                        // [128][128]
    float* Ys  = sm + EMB * EMB;            // [256][128]
    float* scs = Ys + MT * EMB;             // [128]
    float* shs = scs + EMB;                 // [128]

    int tid = threadIdx.x;
    int row0 = blockIdx.x * MT;

    if (tid < EMB)            scs[tid] = g_scale[tid];
    else if (tid < 2 * EMB)   shs[tid - EMB] = g_shift[tid - EMB];

    float4* Ws4 = (float4*)Ws;
    const float4* W24 = (const float4*)W2;
    for (int i = tid; i < EMB * EMB / 4; i += 512) Ws4[i] = W24[i];
    __syncthreads();

    float4* Ys4 = (float4*)Ys;
    const float4* Q4 = (const float4*)g_q;
    for (int i = tid; i < MT * 32; i += 512) {
        int r = i >> 5, ch = i & 31;
        int row = row0 + r;
        float4 v = (row < NN) ? Q4[row * 32 + ch] : make_float4(0.f, 0.f, 0.f, 0.f);
        int k0 = ch * 4;
        v.x = fmaxf(fmaf(v.x, scs[k0 + 0], shs[k0 + 0]), 0.f);
        v.y = fmaxf(fmaf(v.y, scs[k0 + 1], shs[k0 + 1]), 0.f);
        v.z = fmaxf(fmaf(v.z, scs[k0 + 2], shs[k0 + 2]), 0.f);
        v.w = fmaxf(fmaf(v.w, scs[k0 + 3], shs[k0 + 3]), 0.f);
        Ys4[i] = v;
    }
    __syncthreads();

    int cg = tid & 15;
    int rg = tid >> 4;
    ull acc[8][4];
#pragma unroll
    for (int j = 0; j < 8; j++)
#pragma unroll
        for (int q = 0; q < 4; q++) acc[j][q] = 0ull;

    const float* zb = Ys + rg * 8 * EMB;
#pragma unroll 4
    for (int k = 0; k < EMB; k++) {
        const ull* wp = (const ull*)(Ws + k * EMB + cg * 8);
        ull w01 = wp[0], w23 = wp[1], w45 = wp[2], w67 = wp[3];
#pragma unroll
        for (int j = 0; j < 8; j++) {
            float z = zb[j * EMB + k];
            ull zz = pk2(z, z);
            fma2(acc[j][0], zz, w01);
            fma2(acc[j][1], zz, w23);
            fma2(acc[j][2], zz, w45);
            fma2(acc[j][3], zz, w67);
        }
    }

    float4 bA = ((const float4*)b2)[cg * 2], bB = ((const float4*)b2)[cg * 2 + 1];
#pragma unroll
    for (int j = 0; j < 8; j++) {
        int row = row0 + rg * 8 + j;
        if (row < NN) {
            float o[8];
            upk2(acc[j][0], o[0], o[1]);
            upk2(acc[j][1], o[2], o[3]);
            upk2(acc[j][2], o[4], o[5]);
            upk2(acc[j][3], o[6], o[7]);
            float4 oA, oB;
            oA.x = o[0] + bA.x; oA.y = o[1] + bA.y;
            oA.z = o[2] + bA.z; oA.w = o[3] + bA.w;
            oB.x = o[4] + bB.x; oB.y = o[5] + bB.y;
            oB.z = o[6] + bB.z; oB.w = o[7] + bB.w;
            ((float4*)out)[row * 32 + cg * 2]     = oA;
            ((float4*)out)[row * 32 + cg * 2 + 1] = oB;
        }
    }
}

// ---------------- launch ---------------------------------------------------
extern "C" void kernel_launch(void* const* d_in, const int* in_sizes, int n_in,
                              void* d_out, int out_size) {
    const float* x     = (const float*)d_in[0];
    const float* c     = (const float*)d_in[1];
    const void*  ei    = d_in[2];
    const float* cW    = (const float*)d_in[3];
    const float* cb    = (const float*)d_in[4];
    const float* eps   = (const float*)d_in[5];
    const float* W1    = (const float*)d_in[6];
    const float* b1    = (const float*)d_in[7];
    const float* gamma = (const float*)d_in[8];
    const float* beta  = (const float*)d_in[9];
    const float* W2    = (const float*)d_in[10];
    const float* b2    = (const float*)d_in[11];
    float* out = (float*)d_out;

    // one-time side-stream/events (host objects, not device memory)
    static cudaStream_t s2 = nullptr;
    static cudaEvent_t evFork = nullptr, evJoin = nullptr;
    if (s2 == nullptr) {
        cudaStreamCreateWithFlags(&s2, cudaStreamNonBlocking);
        cudaEventCreateWithFlags(&evFork, cudaEventDisableTiming);
        cudaEventCreateWithFlags(&evJoin, cudaEventDisableTiming);
    }

    const int SMEM_A = (EMB * EMB + MT * EMB) * 4;            // 196608
    const int SMEM_2 = (EMB * EMB + MT * EMB + 2 * EMB) * 4;  // 197632
    cudaFuncSetAttribute(gemmA_kernel, cudaFuncAttributeMaxDynamicSharedMemorySize, SMEM_A);
    cudaFuncSetAttribute(gemm2_kernel, cudaFuncAttributeMaxDynamicSharedMemorySize, SMEM_2);

    int gemm_blocks = (NN + MT - 1) / MT;  // 391

    // common prefix (captured stream)
    init_kernel<<<NNP / 256, 256>>>((const int*)ei, cW, cb, W1);

    // fork: CSR build on side stream, gemmA on main stream
    cudaEventRecord(evFork, 0);
    cudaStreamWaitEvent(s2, evFork, 0);

    hist_kernel<<<1024, 256, 0, s2>>>(ei);
    scan1_kernel<<<NBLK_SCAN, 256, 0, s2>>>();
    scan2_kernel<<<1, 512, 0, s2>>>();
    scan3_kernel<<<NBLK_SCAN, 256, 0, s2>>>();
    fill_kernel<<<1024, 256, 0, s2>>>(ei);
    cudaEventRecord(evJoin, s2);

    gemmA_kernel<<<gemm_blocks, 512, SMEM_A>>>(x, c, W1);

    // join
    cudaStreamWaitEvent(0, evJoin, 0);

    gather_kernel<<<1184, 256>>>(eps, b1);
    finalize_kernel<<<1, 128>>>(gamma, beta);
    gemm2_kernel<<<gemm_blocks, 512, SMEM_2>>>(W2, b2, out);
}